// round 10
// baseline (speedup 1.0000x reference)
#include <cuda_runtime.h>
#include <stdint.h>

#define N_MAX 100000
#define E_MAX 800000

// Scratch (device globals; no allocation allowed in kernel_launch)
__device__ float g_bufA[(size_t)N_MAX * 64];
__device__ float g_bufB[(size_t)N_MAX * 64];
__device__ float g_h3[(size_t)N_MAX * 7];
__device__ float g_dinv[N_MAX];
__device__ int   g_deg[N_MAX];
__device__ int   g_ptr[N_MAX];
__device__ int   g_fill[N_MAX];
__device__ int   g_csr[E_MAX];
__device__ int   g_blockSums[512];

// ---------------------------------------------------------------------------
// degree
// ---------------------------------------------------------------------------
__global__ void k_zero_deg(int n) {
    int i = blockIdx.x * blockDim.x + threadIdx.x;
    if (i < n) g_deg[i] = 0;
}

__global__ void k_count_deg(const int* __restrict__ ei, int nE) {
    int e = blockIdx.x * blockDim.x + threadIdx.x;
    if (e < nE) atomicAdd(&g_deg[ei[nE + e]], 1);
}

// ---------------------------------------------------------------------------
// CSR build: scanA computes per-block degree sums; scanC reduces its own
// block-sum prefix, does the intra-block scan, writes ptr/fill + dinv.
// ---------------------------------------------------------------------------
__global__ void k_scanA(int n) {
    __shared__ int sh[256];
    int i = blockIdx.x * 256 + threadIdx.x;
    int t = threadIdx.x;
    sh[t] = (i < n) ? g_deg[i] : 0;
    __syncthreads();
    for (int s = 128; s > 0; s >>= 1) {
        if (t < s) sh[t] += sh[t + s];
        __syncthreads();
    }
    if (t == 0) g_blockSums[blockIdx.x] = sh[0];
}

__global__ void k_scanC(int n) {
    __shared__ int sh[256];
    __shared__ int blockOff;
    int i = blockIdx.x * 256 + threadIdx.x;
    int t = threadIdx.x;

    int partial = 0;
    for (int j = t; j < blockIdx.x; j += 256) partial += g_blockSums[j];
    sh[t] = partial;
    __syncthreads();
    for (int s = 128; s > 0; s >>= 1) {
        if (t < s) sh[t] += sh[t + s];
        __syncthreads();
    }
    if (t == 0) blockOff = sh[0];
    __syncthreads();

    int v = (i < n) ? g_deg[i] : 0;
    sh[t] = v;
    __syncthreads();
    for (int off = 1; off < 256; off <<= 1) {
        int x = (t >= off) ? sh[t - off] : 0;
        __syncthreads();
        sh[t] += x;
        __syncthreads();
    }
    if (i < n) {
        int excl = sh[t] - v + blockOff;
        g_ptr[i]  = excl;
        g_fill[i] = excl;
        g_dinv[i] = rsqrtf((float)v + 1.0f);
    }
}

__global__ void k_fill(const int* __restrict__ ei, int nE) {
    int e = blockIdx.x * blockDim.x + threadIdx.x;
    if (e < nE) {
        int s = ei[e];
        int d = ei[nE + e];
        int pos = atomicAdd(&g_fill[d], 1);
        g_csr[pos] = s;
    }
}

// ---------------------------------------------------------------------------
// f32x2 helpers
// ---------------------------------------------------------------------------
__device__ __forceinline__ unsigned long long pack_dup(float v) {
    unsigned long long r;
    asm("mov.b64 %0, {%1, %1};" : "=l"(r) : "f"(v));
    return r;
}
__device__ __forceinline__ void ffma2(unsigned long long& acc,
                                      unsigned long long a,
                                      unsigned long long b) {
    asm("fma.rn.f32x2 %0, %1, %2, %0;" : "+l"(acc) : "l"(a), "l"(b));
}

// ---------------------------------------------------------------------------
// GEMM: [n x K] @ [K x 64] -> h_out [n x 64]
// Block tile 128 rows x 64 cols, 256 threads, thread tile 4 rows x 8 cols.
// xs transposed [k][row] pad 132 (16B-aligned rows, 2-way store conflicts).
// ---------------------------------------------------------------------------
template <int K, bool RELU>
__global__ void __launch_bounds__(256) k_gemm64(
    const float* __restrict__ in, const float* __restrict__ W,
    float* __restrict__ h_out, int n)
{
    constexpr int KC = 32;
    __shared__ float xs[KC][132];   // [k][row 0..127]
    __shared__ float ws[KC][64];    // [k][col]

    int tid = threadIdx.x;
    int tx = tid & 7;               // col group: 8 cols
    int ty = tid >> 3;              // row group: 4 rows (0..31)
    int rowBase = blockIdx.x * 128;
    int r0 = ty * 4, c0 = tx * 8;

    unsigned long long acc2[4][4];
#pragma unroll
    for (int i = 0; i < 4; i++)
#pragma unroll
        for (int j = 0; j < 4; j++) acc2[i][j] = 0ull;

    int lr = tid >> 1;              // 0..127 (row)
    int lk = (tid & 1) * 16;        // 0 or 16 (k offset)

    for (int k0 = 0; k0 < K; k0 += KC) {
        // stage x tile: each thread loads 16 floats of one row (4 float4)
        {
            int grow = rowBase + lr;
#pragma unroll
            for (int q = 0; q < 4; q++) {
                float4 v = make_float4(0.f, 0.f, 0.f, 0.f);
                if (grow < n)
                    v = *(const float4*)(in + (size_t)grow * K + k0 + lk + q * 4);
                if (RELU) {
                    v.x = fmaxf(v.x, 0.f); v.y = fmaxf(v.y, 0.f);
                    v.z = fmaxf(v.z, 0.f); v.w = fmaxf(v.w, 0.f);
                }
                int kq = lk + q * 4;
                xs[kq + 0][lr] = v.x; xs[kq + 1][lr] = v.y;
                xs[kq + 2][lr] = v.z; xs[kq + 3][lr] = v.w;
            }
        }
        // stage W tile: 32x64 = 512 float4, 2 per thread
        {
            int lkk = tid >> 3;
            int lc  = (tid & 7) * 8;
            const float* p = W + (size_t)(k0 + lkk) * 64 + lc;
            float4 w0 = *(const float4*)p;
            float4 w1 = *(const float4*)(p + 4);
            *(float4*)&ws[lkk][lc]     = w0;
            *(float4*)&ws[lkk][lc + 4] = w1;
        }
        __syncthreads();
#pragma unroll
        for (int kk = 0; kk < KC; kk++) {
            float4 xv = *(const float4*)&xs[kk][r0];
            const unsigned long long* wp =
                (const unsigned long long*)&ws[kk][c0];
            unsigned long long w0 = wp[0], w1 = wp[1];
            unsigned long long w2 = wp[2], w3 = wp[3];
            unsigned long long x0 = pack_dup(xv.x);
            unsigned long long x1 = pack_dup(xv.y);
            unsigned long long x2 = pack_dup(xv.z);
            unsigned long long x3 = pack_dup(xv.w);
            ffma2(acc2[0][0], x0, w0); ffma2(acc2[0][1], x0, w1);
            ffma2(acc2[0][2], x0, w2); ffma2(acc2[0][3], x0, w3);
            ffma2(acc2[1][0], x1, w0); ffma2(acc2[1][1], x1, w1);
            ffma2(acc2[1][2], x1, w2); ffma2(acc2[1][3], x1, w3);
            ffma2(acc2[2][0], x2, w0); ffma2(acc2[2][1], x2, w1);
            ffma2(acc2[2][2], x2, w2); ffma2(acc2[2][3], x2, w3);
            ffma2(acc2[3][0], x3, w0); ffma2(acc2[3][1], x3, w1);
            ffma2(acc2[3][2], x3, w2); ffma2(acc2[3][3], x3, w3);
        }
        __syncthreads();
    }

#pragma unroll
    for (int i = 0; i < 4; i++) {
        int grow = rowBase + r0 + i;
        if (grow < n) {
            float* dst = h_out + (size_t)grow * 64 + c0;
#pragma unroll
            for (int q = 0; q < 2; q++) {
                float4 hv;
                hv.x = __uint_as_float((unsigned)(acc2[i][2*q+0] & 0xffffffffull));
                hv.y = __uint_as_float((unsigned)(acc2[i][2*q+0] >> 32));
                hv.z = __uint_as_float((unsigned)(acc2[i][2*q+1] & 0xffffffffull));
                hv.w = __uint_as_float((unsigned)(acc2[i][2*q+1] >> 32));
                *(float4*)(dst + q * 4) = hv;
            }
        }
    }
}

// ---------------------------------------------------------------------------
// CSR pull aggregation (64-wide): one warp per dst node.
// out[d] = b + h[d]*dinv[d]^2 + sum_{s in N(d)} h[s]*dinv[s]*dinv[d]
// ---------------------------------------------------------------------------
__global__ void __launch_bounds__(256) k_agg64_csr(
    const float* __restrict__ h, const float* __restrict__ b,
    float* __restrict__ out, int n)
{
    int warp = (blockIdx.x * 256 + threadIdx.x) >> 5;
    int lane = threadIdx.x & 31;
    if (warp >= n) return;
    int d = warp;

    float dd = g_dinv[d];
    int start = g_ptr[d];
    int deg   = g_deg[d];

    float2 hv = *(const float2*)(h + (size_t)d * 64 + lane * 2);
    float d2 = dd * dd;
    float2 acc;
    acc.x = fmaf(hv.x, d2, b[lane * 2]);
    acc.y = fmaf(hv.y, d2, b[lane * 2 + 1]);

    for (int base = 0; base < deg; base += 32) {
        int cnt = min(32, deg - base);
        int s = 0; float w = 0.f;
        if (lane < cnt) {
            s = g_csr[start + base + lane];
            w = g_dinv[s];
        }
#pragma unroll 4
        for (int j = 0; j < cnt; j++) {
            int   sj = __shfl_sync(0xffffffffu, s, j);
            float wj = __shfl_sync(0xffffffffu, w, j);
            float coef = wj * dd;
            float2 hs = *(const float2*)(h + (size_t)sj * 64 + lane * 2);
            acc.x = fmaf(hs.x, coef, acc.x);
            acc.y = fmaf(hs.y, coef, acc.y);
        }
    }
    *(float2*)(out + (size_t)d * 64 + lane * 2) = acc;
}

// ---------------------------------------------------------------------------
// Layer 3 GEMM: relu(in[n x 64]) @ W3[64 x 7] -> h3 only
// ---------------------------------------------------------------------------
__global__ void __launch_bounds__(256) k_gemm7(
    const float* __restrict__ in, const float* __restrict__ W,
    float* __restrict__ h_out, int n)
{
    __shared__ float wsh[64 * 7];
    int tid = threadIdx.x;
    for (int i = tid; i < 448; i += 256) wsh[i] = W[i];
    __syncthreads();

    int row = blockIdx.x * blockDim.x + tid;
    if (row >= n) return;

    float acc[7];
#pragma unroll
    for (int c = 0; c < 7; c++) acc[c] = 0.f;

    const float* p = in + (size_t)row * 64;
#pragma unroll
    for (int k = 0; k < 64; k += 4) {
        float4 v = *(const float4*)(p + k);
        v.x = fmaxf(v.x, 0.f); v.y = fmaxf(v.y, 0.f);
        v.z = fmaxf(v.z, 0.f); v.w = fmaxf(v.w, 0.f);
#pragma unroll
        for (int c = 0; c < 7; c++) {
            acc[c] = fmaf(v.x, wsh[(k + 0) * 7 + c], acc[c]);
            acc[c] = fmaf(v.y, wsh[(k + 1) * 7 + c], acc[c]);
            acc[c] = fmaf(v.z, wsh[(k + 2) * 7 + c], acc[c]);
            acc[c] = fmaf(v.w, wsh[(k + 3) * 7 + c], acc[c]);
        }
    }
#pragma unroll
    for (int c = 0; c < 7; c++)
        h_out[(size_t)row * 7 + c] = acc[c];
}

// ---------------------------------------------------------------------------
// CSR pull aggregation (7-wide): one warp per dst node, lanes 0..6 hold cols.
// ---------------------------------------------------------------------------
__global__ void __launch_bounds__(256) k_agg7_csr(
    const float* __restrict__ h, const float* __restrict__ b,
    float* __restrict__ out, int n)
{
    int warp = (blockIdx.x * 256 + threadIdx.x) >> 5;
    int lane = threadIdx.x & 31;
    if (warp >= n) return;
    int d = warp;

    float dd = g_dinv[d];
    int start = g_ptr[d];
    int deg   = g_deg[d];

    float acc = 0.f;
    if (lane < 7)
        acc = fmaf(h[(size_t)d * 7 + lane], dd * dd, b[lane]);

    for (int base = 0; base < deg; base += 32) {
        int cnt = min(32, deg - base);
        int s = 0; float w = 0.f;
        if (lane < cnt) {
            s = g_csr[start + base + lane];
            w = g_dinv[s];
        }
        for (int j = 0; j < cnt; j++) {
            int   sj = __shfl_sync(0xffffffffu, s, j);
            float wj = __shfl_sync(0xffffffffu, w, j);
            if (lane < 7)
                acc = fmaf(h[(size_t)sj * 7 + lane], wj * dd, acc);
        }
    }
    if (lane < 7)
        out[(size_t)d * 7 + lane] = acc;
}

// ---------------------------------------------------------------------------
// launch
// ---------------------------------------------------------------------------
extern "C" void kernel_launch(void* const* d_in, const int* in_sizes, int n_in,
                              void* d_out, int out_size)
{
    const float* x  = (const float*)d_in[0];
    const int*   ei = (const int*)d_in[1];
    const float* W1 = (const float*)d_in[2];
    const float* b1 = (const float*)d_in[3];
    const float* W2 = (const float*)d_in[4];
    const float* b2 = (const float*)d_in[5];
    const float* W3 = (const float*)d_in[6];
    const float* b3 = (const float*)d_in[7];

    int n  = in_sizes[0] / 128;
    int nE = in_sizes[1] / 2;
    float* out = (float*)d_out;

    float *bufA, *bufB, *h3;
    cudaGetSymbolAddress((void**)&bufA, g_bufA);
    cudaGetSymbolAddress((void**)&bufB, g_bufB);
    cudaGetSymbolAddress((void**)&h3,   g_h3);

    int nb_n = (n + 255) / 256;
    int nb_e = (nE + 255) / 256;
    int nb_g = (n + 127) / 128;                          // 128-row GEMM tiles
    int nb_w = (int)(((long long)n * 32 + 255) / 256);

    // degree + CSR + dinv (once, reused by all 3 layers)
    k_zero_deg<<<nb_n, 256>>>(n);
    k_count_deg<<<nb_e, 256>>>(ei, nE);
    k_scanA<<<nb_n, 256>>>(n);
    k_scanC<<<nb_n, 256>>>(n);
    k_fill<<<nb_e, 256>>>(ei, nE);

    // layer 1: h1 = x@W1 -> bufA ; bufB = agg(h1) + b1
    k_gemm64<128, false><<<nb_g, 256>>>(x, W1, bufA, n);
    k_agg64_csr<<<nb_w, 256>>>(bufA, b1, bufB, n);

    // layer 2: h2 = relu(bufB)@W2 -> bufA ; bufB = agg(h2) + b2
    k_gemm64<64, true><<<nb_g, 256>>>(bufB, W2, bufA, n);
    k_agg64_csr<<<nb_w, 256>>>(bufA, b2, bufB, n);

    // layer 3: h3 = relu(bufB)@W3 ; d_out = agg(h3) + b3
    k_gemm7<<<nb_n, 256>>>(bufB, W3, h3, n);
    k_agg7_csr<<<nb_w, 256>>>(ei ? h3 : h3, b3, out, n);
}

// round 12
// speedup vs baseline: 1.1715x; 1.1715x over previous
#include <cuda_runtime.h>
#include <stdint.h>

#define N_MAX 100000
#define E_MAX 800000

// Scratch (device globals; no allocation allowed in kernel_launch)
__device__ float g_bufA[(size_t)N_MAX * 64];
__device__ float g_bufB[(size_t)N_MAX * 64];
__device__ float g_h3[(size_t)N_MAX * 7];
__device__ float g_dinv[N_MAX];
__device__ int   g_deg[N_MAX];
__device__ int   g_ptr[N_MAX];
__device__ int   g_fill[N_MAX];
__device__ int   g_csr[E_MAX];
__device__ int   g_blockSums[512];

// ---------------------------------------------------------------------------
// degree
// ---------------------------------------------------------------------------
__global__ void k_zero_deg(int n) {
    int i = blockIdx.x * blockDim.x + threadIdx.x;
    if (i < n) g_deg[i] = 0;
}

__global__ void k_count_deg(const int* __restrict__ ei, int nE) {
    int e = blockIdx.x * blockDim.x + threadIdx.x;
    if (e < nE) atomicAdd(&g_deg[ei[nE + e]], 1);
}

// ---------------------------------------------------------------------------
// CSR build
// ---------------------------------------------------------------------------
__global__ void k_scanA(int n) {
    __shared__ int sh[256];
    int i = blockIdx.x * 256 + threadIdx.x;
    int t = threadIdx.x;
    sh[t] = (i < n) ? g_deg[i] : 0;
    __syncthreads();
    for (int s = 128; s > 0; s >>= 1) {
        if (t < s) sh[t] += sh[t + s];
        __syncthreads();
    }
    if (t == 0) g_blockSums[blockIdx.x] = sh[0];
}

__global__ void k_scanC(int n) {
    __shared__ int sh[256];
    __shared__ int blockOff;
    int i = blockIdx.x * 256 + threadIdx.x;
    int t = threadIdx.x;

    int partial = 0;
    for (int j = t; j < blockIdx.x; j += 256) partial += g_blockSums[j];
    sh[t] = partial;
    __syncthreads();
    for (int s = 128; s > 0; s >>= 1) {
        if (t < s) sh[t] += sh[t + s];
        __syncthreads();
    }
    if (t == 0) blockOff = sh[0];
    __syncthreads();

    int v = (i < n) ? g_deg[i] : 0;
    sh[t] = v;
    __syncthreads();
    for (int off = 1; off < 256; off <<= 1) {
        int x = (t >= off) ? sh[t - off] : 0;
        __syncthreads();
        sh[t] += x;
        __syncthreads();
    }
    if (i < n) {
        int excl = sh[t] - v + blockOff;
        g_ptr[i]  = excl;
        g_fill[i] = excl;
        g_dinv[i] = rsqrtf((float)v + 1.0f);
    }
}

__global__ void k_fill(const int* __restrict__ ei, int nE) {
    int e = blockIdx.x * blockDim.x + threadIdx.x;
    if (e < nE) {
        int s = ei[e];
        int d = ei[nE + e];
        int pos = atomicAdd(&g_fill[d], 1);
        g_csr[pos] = s;
    }
}

// ---------------------------------------------------------------------------
// f32x2 helpers
// ---------------------------------------------------------------------------
__device__ __forceinline__ unsigned long long pack_dup(float v) {
    unsigned long long r;
    asm("mov.b64 %0, {%1, %1};" : "=l"(r) : "f"(v));
    return r;
}
__device__ __forceinline__ void ffma2(unsigned long long& acc,
                                      unsigned long long a,
                                      unsigned long long b) {
    asm("fma.rn.f32x2 %0, %1, %2, %0;" : "+l"(acc) : "l"(a), "l"(b));
}

// ---------------------------------------------------------------------------
// GEMM (R8 64x64 tile, software-pipelined): [n x K] @ [K x 64] -> h_out
// Double-buffered smem; next k-tile's global loads prefetched into registers
// before the FFMA loop of the current tile.
// ---------------------------------------------------------------------------
template <int K, bool RELU>
__global__ void __launch_bounds__(256) k_gemm64(
    const float* __restrict__ in, const float* __restrict__ W,
    float* __restrict__ h_out, int n)
{
    constexpr int KC = 32;
    constexpr int NT = K / KC;
    __shared__ float xs[2][KC][72];
    __shared__ float ws[2][KC][64];

    int tid = threadIdx.x;
    int tx = tid & 15, ty = tid >> 4;
    int rowBase = blockIdx.x * 64;
    int r0 = ty * 4, c0 = tx * 4;

    unsigned long long acc2[4][2];
#pragma unroll
    for (int i = 0; i < 4; i++) { acc2[i][0] = 0ull; acc2[i][1] = 0ull; }

    int lr = tid >> 2;           // 0..63 (row)
    int lk = (tid & 3) * 8;      // 0,8,16,24 (k offset)
    int lkk = tid >> 3;          // 0..31
    int lc  = (tid & 7) * 8;     // 0..56

    int growx = rowBase + lr;
    bool rowOK = (growx < n);
    const float* xptr = in + (size_t)growx * K + lk;
    const float* wptr = W + (size_t)lkk * 64 + lc;

    float4 v0, v1, w0, w1;

    // prologue: load tile 0
    {
        if (rowOK) {
            v0 = *(const float4*)(xptr);
            v1 = *(const float4*)(xptr + 4);
        } else {
            v0 = make_float4(0.f, 0.f, 0.f, 0.f);
            v1 = v0;
        }
        w0 = *(const float4*)(wptr);
        w1 = *(const float4*)(wptr + 4);
    }

    int buf = 0;
    // store tile 0
    {
        float4 s0 = v0, s1 = v1;
        if (RELU) {
            s0.x = fmaxf(s0.x, 0.f); s0.y = fmaxf(s0.y, 0.f);
            s0.z = fmaxf(s0.z, 0.f); s0.w = fmaxf(s0.w, 0.f);
            s1.x = fmaxf(s1.x, 0.f); s1.y = fmaxf(s1.y, 0.f);
            s1.z = fmaxf(s1.z, 0.f); s1.w = fmaxf(s1.w, 0.f);
        }
        xs[0][lk + 0][lr] = s0.x; xs[0][lk + 1][lr] = s0.y;
        xs[0][lk + 2][lr] = s0.z; xs[0][lk + 3][lr] = s0.w;
        xs[0][lk + 4][lr] = s1.x; xs[0][lk + 5][lr] = s1.y;
        xs[0][lk + 6][lr] = s1.z; xs[0][lk + 7][lr] = s1.w;
        *(float4*)&ws[0][lkk][lc]     = w0;
        *(float4*)&ws[0][lkk][lc + 4] = w1;
    }
    __syncthreads();

#pragma unroll
    for (int t = 0; t < NT; t++) {
        // prefetch tile t+1 into registers (latency overlapped with compute)
        if (t + 1 < NT) {
            int k0 = (t + 1) * KC;
            if (rowOK) {
                v0 = *(const float4*)(xptr + k0);
                v1 = *(const float4*)(xptr + k0 + 4);
            } else {
                v0 = make_float4(0.f, 0.f, 0.f, 0.f);
                v1 = v0;
            }
            w0 = *(const float4*)(wptr + (size_t)k0 * 64);
            w1 = *(const float4*)(wptr + (size_t)k0 * 64 + 4);
        }

        // compute on smem[buf]
#pragma unroll
        for (int kk = 0; kk < KC; kk++) {
            float4 xv = *(const float4*)&xs[buf][kk][r0];
            const unsigned long long* wp =
                (const unsigned long long*)&ws[buf][kk][c0];
            unsigned long long q0 = wp[0], q1 = wp[1];
            unsigned long long x0 = pack_dup(xv.x);
            unsigned long long x1 = pack_dup(xv.y);
            unsigned long long x2 = pack_dup(xv.z);
            unsigned long long x3 = pack_dup(xv.w);
            ffma2(acc2[0][0], x0, q0); ffma2(acc2[0][1], x0, q1);
            ffma2(acc2[1][0], x1, q0); ffma2(acc2[1][1], x1, q1);
            ffma2(acc2[2][0], x2, q0); ffma2(acc2[2][1], x2, q1);
            ffma2(acc2[3][0], x3, q0); ffma2(acc2[3][1], x3, q1);
        }

        // store prefetched tile into the other buffer
        if (t + 1 < NT) {
            int nb = buf ^ 1;
            float4 s0 = v0, s1 = v1;
            if (RELU) {
                s0.x = fmaxf(s0.x, 0.f); s0.y = fmaxf(s0.y, 0.f);
                s0.z = fmaxf(s0.z, 0.f); s0.w = fmaxf(s0.w, 0.f);
                s1.x = fmaxf(s1.x, 0.f); s1.y = fmaxf(s1.y, 0.f);
                s1.z = fmaxf(s1.z, 0.f); s1.w = fmaxf(s1.w, 0.f);
            }
            xs[nb][lk + 0][lr] = s0.x; xs[nb][lk + 1][lr] = s0.y;
            xs[nb][lk + 2][lr] = s0.z; xs[nb][lk + 3][lr] = s0.w;
            xs[nb][lk + 4][lr] = s1.x; xs[nb][lk + 5][lr] = s1.y;
            xs[nb][lk + 6][lr] = s1.z; xs[nb][lk + 7][lr] = s1.w;
            *(float4*)&ws[nb][lkk][lc]     = w0;
            *(float4*)&ws[nb][lkk][lc + 4] = w1;
            __syncthreads();
            buf = nb;
        }
    }

#pragma unroll
    for (int i = 0; i < 4; i++) {
        int grow = rowBase + r0 + i;
        if (grow < n) {
            float4 hv;
            hv.x = __uint_as_float((unsigned)(acc2[i][0] & 0xffffffffull));
            hv.y = __uint_as_float((unsigned)(acc2[i][0] >> 32));
            hv.z = __uint_as_float((unsigned)(acc2[i][1] & 0xffffffffull));
            hv.w = __uint_as_float((unsigned)(acc2[i][1] >> 32));
            *(float4*)&h_out[(size_t)grow * 64 + c0] = hv;
        }
    }
}

// ---------------------------------------------------------------------------
// CSR pull aggregation (64-wide): one warp per dst node.
// out[d] = b + h[d]*dinv[d]^2 + sum_{s in N(d)} h[s]*dinv[s]*dinv[d]
// ---------------------------------------------------------------------------
__global__ void __launch_bounds__(256) k_agg64_csr(
    const float* __restrict__ h, const float* __restrict__ b,
    float* __restrict__ out, int n)
{
    int warp = (blockIdx.x * 256 + threadIdx.x) >> 5;
    int lane = threadIdx.x & 31;
    if (warp >= n) return;
    int d = warp;

    float dd = g_dinv[d];
    int start = g_ptr[d];
    int deg   = g_deg[d];

    float2 hv = *(const float2*)(h + (size_t)d * 64 + lane * 2);
    float d2 = dd * dd;
    float2 acc;
    acc.x = fmaf(hv.x, d2, b[lane * 2]);
    acc.y = fmaf(hv.y, d2, b[lane * 2 + 1]);

    for (int base = 0; base < deg; base += 32) {
        int cnt = min(32, deg - base);
        int s = 0; float w = 0.f;
        if (lane < cnt) {
            s = g_csr[start + base + lane];
            w = g_dinv[s];
        }
#pragma unroll 4
        for (int j = 0; j < cnt; j++) {
            int   sj = __shfl_sync(0xffffffffu, s, j);
            float wj = __shfl_sync(0xffffffffu, w, j);
            float coef = wj * dd;
            float2 hs = *(const float2*)(h + (size_t)sj * 64 + lane * 2);
            acc.x = fmaf(hs.x, coef, acc.x);
            acc.y = fmaf(hs.y, coef, acc.y);
        }
    }
    *(float2*)(out + (size_t)d * 64 + lane * 2) = acc;
}

// ---------------------------------------------------------------------------
// Layer 3 GEMM: relu(in[n x 64]) @ W3[64 x 7] -> h3 only
// ---------------------------------------------------------------------------
__global__ void __launch_bounds__(256) k_gemm7(
    const float* __restrict__ in, const float* __restrict__ W,
    float* __restrict__ h_out, int n)
{
    __shared__ float wsh[64 * 7];
    int tid = threadIdx.x;
    for (int i = tid; i < 448; i += 256) wsh[i] = W[i];
    __syncthreads();

    int row = blockIdx.x * blockDim.x + tid;
    if (row >= n) return;

    float acc[7];
#pragma unroll
    for (int c = 0; c < 7; c++) acc[c] = 0.f;

    const float* p = in + (size_t)row * 64;
#pragma unroll
    for (int k = 0; k < 64; k += 4) {
        float4 v = *(const float4*)(p + k);
        v.x = fmaxf(v.x, 0.f); v.y = fmaxf(v.y, 0.f);
        v.z = fmaxf(v.z, 0.f); v.w = fmaxf(v.w, 0.f);
#pragma unroll
        for (int c = 0; c < 7; c++) {
            acc[c] = fmaf(v.x, wsh[(k + 0) * 7 + c], acc[c]);
            acc[c] = fmaf(v.y, wsh[(k + 1) * 7 + c], acc[c]);
            acc[c] = fmaf(v.z, wsh[(k + 2) * 7 + c], acc[c]);
            acc[c] = fmaf(v.w, wsh[(k + 3) * 7 + c], acc[c]);
        }
    }
#pragma unroll
    for (int c = 0; c < 7; c++)
        h_out[(size_t)row * 7 + c] = acc[c];
}

// ---------------------------------------------------------------------------
// CSR pull aggregation (7-wide): one warp per dst node, lanes 0..6 hold cols.
// ---------------------------------------------------------------------------
__global__ void __launch_bounds__(256) k_agg7_csr(
    const float* __restrict__ h, const float* __restrict__ b,
    float* __restrict__ out, int n)
{
    int warp = (blockIdx.x * 256 + threadIdx.x) >> 5;
    int lane = threadIdx.x & 31;
    if (warp >= n) return;
    int d = warp;

    float dd = g_dinv[d];
    int start = g_ptr[d];
    int deg   = g_deg[d];

    float acc = 0.f;
    if (lane < 7)
        acc = fmaf(h[(size_t)d * 7 + lane], dd * dd, b[lane]);

    for (int base = 0; base < deg; base += 32) {
        int cnt = min(32, deg - base);
        int s = 0; float w = 0.f;
        if (lane < cnt) {
            s = g_csr[start + base + lane];
            w = g_dinv[s];
        }
        for (int j = 0; j < cnt; j++) {
            int   sj = __shfl_sync(0xffffffffu, s, j);
            float wj = __shfl_sync(0xffffffffu, w, j);
            if (lane < 7)
                acc = fmaf(h[(size_t)sj * 7 + lane], wj * dd, acc);
        }
    }
    if (lane < 7)
        out[(size_t)d * 7 + lane] = acc;
}

// ---------------------------------------------------------------------------
// launch
// ---------------------------------------------------------------------------
extern "C" void kernel_launch(void* const* d_in, const int* in_sizes, int n_in,
                              void* d_out, int out_size)
{
    const float* x  = (const float*)d_in[0];
    const int*   ei = (const int*)d_in[1];
    const float* W1 = (const float*)d_in[2];
    const float* b1 = (const float*)d_in[3];
    const float* W2 = (const float*)d_in[4];
    const float* b2 = (const float*)d_in[5];
    const float* W3 = (const float*)d_in[6];
    const float* b3 = (const float*)d_in[7];

    int n  = in_sizes[0] / 128;
    int nE = in_sizes[1] / 2;
    float* out = (float*)d_out;

    float *bufA, *bufB, *h3;
    cudaGetSymbolAddress((void**)&bufA, g_bufA);
    cudaGetSymbolAddress((void**)&bufB, g_bufB);
    cudaGetSymbolAddress((void**)&h3,   g_h3);

    int nb_n = (n + 255) / 256;
    int nb_e = (nE + 255) / 256;
    int nb_g = (n + 63) / 64;
    int nb_w = (int)(((long long)n * 32 + 255) / 256);

    // degree + CSR + dinv (once, reused by all 3 layers)
    k_zero_deg<<<nb_n, 256>>>(n);
    k_count_deg<<<nb_e, 256>>>(ei, nE);
    k_scanA<<<nb_n, 256>>>(n);
    k_scanC<<<nb_n, 256>>>(n);
    k_fill<<<nb_e, 256>>>(ei, nE);

    // layer 1: h1 = x@W1 -> bufA ; bufB = agg(h1) + b1
    k_gemm64<128, false><<<nb_g, 256>>>(x, W1, bufA, n);
    k_agg64_csr<<<nb_w, 256>>>(bufA, b1, bufB, n);

    // layer 2: h2 = relu(bufB)@W2 -> bufA ; bufB = agg(h2) + b2
    k_gemm64<64, true><<<nb_g, 256>>>(bufB, W2, bufA, n);
    k_agg64_csr<<<nb_w, 256>>>(bufA, b2, bufB, n);

    // layer 3: h3 = relu(bufB)@W3 ; d_out = agg(h3) + b3
    k_gemm7<<<nb_n, 256>>>(bufB, W3, h3, n);
    k_agg7_csr<<<nb_w, 256>>>(h3, b3, out, n);
}

// round 13
// speedup vs baseline: 1.1946x; 1.0197x over previous
#include <cuda_runtime.h>
#include <stdint.h>

#define N_MAX 100000
#define E_MAX 800000

// Scratch (device globals; no allocation allowed in kernel_launch)
__device__ float g_bufA[(size_t)N_MAX * 64];
__device__ float g_bufB[(size_t)N_MAX * 64];
__device__ float g_h3[(size_t)N_MAX * 7];
__device__ float g_dinv[N_MAX];
__device__ int   g_deg[N_MAX];
__device__ int   g_ptr[N_MAX];
__device__ int   g_fill[N_MAX];
__device__ int   g_csr[E_MAX];
__device__ int   g_blockSums[512];

// ---------------------------------------------------------------------------
// degree (zeroing done by cudaMemsetAsync in kernel_launch)
// ---------------------------------------------------------------------------
__global__ void k_count_deg(const int* __restrict__ ei, int nE) {
    int e = blockIdx.x * blockDim.x + threadIdx.x;
    if (e < nE) atomicAdd(&g_deg[ei[nE + e]], 1);
}

// ---------------------------------------------------------------------------
// CSR build
// ---------------------------------------------------------------------------
__global__ void k_scanA(int n) {
    __shared__ int sh[256];
    int i = blockIdx.x * 256 + threadIdx.x;
    int t = threadIdx.x;
    sh[t] = (i < n) ? g_deg[i] : 0;
    __syncthreads();
    for (int s = 128; s > 0; s >>= 1) {
        if (t < s) sh[t] += sh[t + s];
        __syncthreads();
    }
    if (t == 0) g_blockSums[blockIdx.x] = sh[0];
}

__global__ void k_scanC(int n) {
    __shared__ int sh[256];
    __shared__ int blockOff;
    int i = blockIdx.x * 256 + threadIdx.x;
    int t = threadIdx.x;

    int partial = 0;
    for (int j = t; j < blockIdx.x; j += 256) partial += g_blockSums[j];
    sh[t] = partial;
    __syncthreads();
    for (int s = 128; s > 0; s >>= 1) {
        if (t < s) sh[t] += sh[t + s];
        __syncthreads();
    }
    if (t == 0) blockOff = sh[0];
    __syncthreads();

    int v = (i < n) ? g_deg[i] : 0;
    sh[t] = v;
    __syncthreads();
    for (int off = 1; off < 256; off <<= 1) {
        int x = (t >= off) ? sh[t - off] : 0;
        __syncthreads();
        sh[t] += x;
        __syncthreads();
    }
    if (i < n) {
        int excl = sh[t] - v + blockOff;
        g_ptr[i]  = excl;
        g_fill[i] = excl;
        g_dinv[i] = rsqrtf((float)v + 1.0f);
    }
}

__global__ void k_fill(const int* __restrict__ ei, int nE) {
    int e = blockIdx.x * blockDim.x + threadIdx.x;
    if (e < nE) {
        int s = ei[e];
        int d = ei[nE + e];
        int pos = atomicAdd(&g_fill[d], 1);
        g_csr[pos] = s;
    }
}

// ---------------------------------------------------------------------------
// f32x2 helpers
// ---------------------------------------------------------------------------
__device__ __forceinline__ unsigned long long pack_dup(float v) {
    unsigned long long r;
    asm("mov.b64 %0, {%1, %1};" : "=l"(r) : "f"(v));
    return r;
}
__device__ __forceinline__ void ffma2(unsigned long long& acc,
                                      unsigned long long a,
                                      unsigned long long b) {
    asm("fma.rn.f32x2 %0, %1, %2, %0;" : "+l"(acc) : "l"(a), "l"(b));
}

// ---------------------------------------------------------------------------
// GEMM (R8-proven shape + xs XOR swizzle): [n x K] @ [K x 64] -> h_out
// Block: 256 threads, tile 64 rows x 64 cols, thread tile 4x4, f32x2 FFMA2.
// xs row index XOR-swizzled by (k & 24): staging STS.32 conflict-free,
// reads stay aligned/contiguous ( ((r0^c)+j)^c == r0+j for r0 % 4 == 0 ).
// ---------------------------------------------------------------------------
template <int K, bool RELU>
__global__ void __launch_bounds__(256) k_gemm64(
    const float* __restrict__ in, const float* __restrict__ W,
    float* __restrict__ h_out, int n)
{
    constexpr int KC = 32;
    __shared__ float xs[KC][72];
    __shared__ float ws[KC][64];

    int tid = threadIdx.x;
    int tx = tid & 15, ty = tid >> 4;
    int rowBase = blockIdx.x * 64;
    int r0 = ty * 4, c0 = tx * 4;

    unsigned long long acc2[4][2];
#pragma unroll
    for (int i = 0; i < 4; i++) { acc2[i][0] = 0ull; acc2[i][1] = 0ull; }

    int lr = tid >> 2;
    int lk = (tid & 3) * 8;

    for (int k0 = 0; k0 < K; k0 += KC) {
        {
            int grow = rowBase + lr;
            float4 v0, v1;
            if (grow < n) {
                const float* p = in + (size_t)grow * K + k0 + lk;
                v0 = *(const float4*)p;
                v1 = *(const float4*)(p + 4);
            } else {
                v0 = make_float4(0.f, 0.f, 0.f, 0.f);
                v1 = v0;
            }
            if (RELU) {
                v0.x = fmaxf(v0.x, 0.f); v0.y = fmaxf(v0.y, 0.f);
                v0.z = fmaxf(v0.z, 0.f); v0.w = fmaxf(v0.w, 0.f);
                v1.x = fmaxf(v1.x, 0.f); v1.y = fmaxf(v1.y, 0.f);
                v1.z = fmaxf(v1.z, 0.f); v1.w = fmaxf(v1.w, 0.f);
            }
            // XOR-swizzled rows: k = lk+i, c(k) = k & 24
            xs[lk + 0][lr ^ ((lk + 0) & 24)] = v0.x;
            xs[lk + 1][lr ^ ((lk + 1) & 24)] = v0.y;
            xs[lk + 2][lr ^ ((lk + 2) & 24)] = v0.z;
            xs[lk + 3][lr ^ ((lk + 3) & 24)] = v0.w;
            xs[lk + 4][lr ^ ((lk + 4) & 24)] = v1.x;
            xs[lk + 5][lr ^ ((lk + 5) & 24)] = v1.y;
            xs[lk + 6][lr ^ ((lk + 6) & 24)] = v1.z;
            xs[lk + 7][lr ^ ((lk + 7) & 24)] = v1.w;
        }
        {
            int lkk = tid >> 3;
            int lc  = (tid & 7) * 8;
            const float* p = W + (size_t)(k0 + lkk) * 64 + lc;
            float4 w0 = *(const float4*)p;
            float4 w1 = *(const float4*)(p + 4);
            *(float4*)&ws[lkk][lc]     = w0;
            *(float4*)&ws[lkk][lc + 4] = w1;
        }
        __syncthreads();
#pragma unroll
        for (int kk = 0; kk < KC; kk++) {
            float4 xv = *(const float4*)&xs[kk][r0 ^ (kk & 24)];
            const unsigned long long* wp =
                (const unsigned long long*)&ws[kk][c0];
            unsigned long long w0 = wp[0], w1 = wp[1];
            unsigned long long x0 = pack_dup(xv.x);
            unsigned long long x1 = pack_dup(xv.y);
            unsigned long long x2 = pack_dup(xv.z);
            unsigned long long x3 = pack_dup(xv.w);
            ffma2(acc2[0][0], x0, w0); ffma2(acc2[0][1], x0, w1);
            ffma2(acc2[1][0], x1, w0); ffma2(acc2[1][1], x1, w1);
            ffma2(acc2[2][0], x2, w0); ffma2(acc2[2][1], x2, w1);
            ffma2(acc2[3][0], x3, w0); ffma2(acc2[3][1], x3, w1);
        }
        __syncthreads();
    }

#pragma unroll
    for (int i = 0; i < 4; i++) {
        int grow = rowBase + r0 + i;
        if (grow < n) {
            float4 hv;
            hv.x = __uint_as_float((unsigned)(acc2[i][0] & 0xffffffffull));
            hv.y = __uint_as_float((unsigned)(acc2[i][0] >> 32));
            hv.z = __uint_as_float((unsigned)(acc2[i][1] & 0xffffffffull));
            hv.w = __uint_as_float((unsigned)(acc2[i][1] >> 32));
            *(float4*)&h_out[(size_t)grow * 64 + c0] = hv;
        }
    }
}

// ---------------------------------------------------------------------------
// CSR pull aggregation (64-wide): one warp per dst node.
// out[d] = b + h[d]*dinv[d]^2 + sum_{s in N(d)} h[s]*dinv[s]*dinv[d]
// ---------------------------------------------------------------------------
__global__ void __launch_bounds__(256) k_agg64_csr(
    const float* __restrict__ h, const float* __restrict__ b,
    float* __restrict__ out, int n)
{
    int warp = (blockIdx.x * 256 + threadIdx.x) >> 5;
    int lane = threadIdx.x & 31;
    if (warp >= n) return;
    int d = warp;

    float dd = g_dinv[d];
    int start = g_ptr[d];
    int deg   = g_deg[d];

    float2 hv = *(const float2*)(h + (size_t)d * 64 + lane * 2);
    float d2 = dd * dd;
    float2 acc;
    acc.x = fmaf(hv.x, d2, b[lane * 2]);
    acc.y = fmaf(hv.y, d2, b[lane * 2 + 1]);

    for (int base = 0; base < deg; base += 32) {
        int cnt = min(32, deg - base);
        int s = 0; float w = 0.f;
        if (lane < cnt) {
            s = g_csr[start + base + lane];
            w = g_dinv[s];
        }
#pragma unroll 4
        for (int j = 0; j < cnt; j++) {
            int   sj = __shfl_sync(0xffffffffu, s, j);
            float wj = __shfl_sync(0xffffffffu, w, j);
            float coef = wj * dd;
            float2 hs = *(const float2*)(h + (size_t)sj * 64 + lane * 2);
            acc.x = fmaf(hs.x, coef, acc.x);
            acc.y = fmaf(hs.y, coef, acc.y);
        }
    }
    *(float2*)(out + (size_t)d * 64 + lane * 2) = acc;
}

// ---------------------------------------------------------------------------
// Layer 3 GEMM: relu(in[n x 64]) @ W3[64 x 7] -> h3 only
// ---------------------------------------------------------------------------
__global__ void __launch_bounds__(256) k_gemm7(
    const float* __restrict__ in, const float* __restrict__ W,
    float* __restrict__ h_out, int n)
{
    __shared__ float wsh[64 * 7];
    int tid = threadIdx.x;
    for (int i = tid; i < 448; i += 256) wsh[i] = W[i];
    __syncthreads();

    int row = blockIdx.x * blockDim.x + tid;
    if (row >= n) return;

    float acc[7];
#pragma unroll
    for (int c = 0; c < 7; c++) acc[c] = 0.f;

    const float* p = in + (size_t)row * 64;
#pragma unroll
    for (int k = 0; k < 64; k += 4) {
        float4 v = *(const float4*)(p + k);
        v.x = fmaxf(v.x, 0.f); v.y = fmaxf(v.y, 0.f);
        v.z = fmaxf(v.z, 0.f); v.w = fmaxf(v.w, 0.f);
#pragma unroll
        for (int c = 0; c < 7; c++) {
            acc[c] = fmaf(v.x, wsh[(k + 0) * 7 + c], acc[c]);
            acc[c] = fmaf(v.y, wsh[(k + 1) * 7 + c], acc[c]);
            acc[c] = fmaf(v.z, wsh[(k + 2) * 7 + c], acc[c]);
            acc[c] = fmaf(v.w, wsh[(k + 3) * 7 + c], acc[c]);
        }
    }
#pragma unroll
    for (int c = 0; c < 7; c++)
        h_out[(size_t)row * 7 + c] = acc[c];
}

// ---------------------------------------------------------------------------
// CSR pull aggregation (7-wide): one warp per dst node, lanes 0..6 hold cols.
// ---------------------------------------------------------------------------
__global__ void __launch_bounds__(256) k_agg7_csr(
    const float* __restrict__ h, const float* __restrict__ b,
    float* __restrict__ out, int n)
{
    int warp = (blockIdx.x * 256 + threadIdx.x) >> 5;
    int lane = threadIdx.x & 31;
    if (warp >= n) return;
    int d = warp;

    float dd = g_dinv[d];
    int start = g_ptr[d];
    int deg   = g_deg[d];

    float acc = 0.f;
    if (lane < 7)
        acc = fmaf(h[(size_t)d * 7 + lane], dd * dd, b[lane]);

    for (int base = 0; base < deg; base += 32) {
        int cnt = min(32, deg - base);
        int s = 0; float w = 0.f;
        if (lane < cnt) {
            s = g_csr[start + base + lane];
            w = g_dinv[s];
        }
        for (int j = 0; j < cnt; j++) {
            int   sj = __shfl_sync(0xffffffffu, s, j);
            float wj = __shfl_sync(0xffffffffu, w, j);
            if (lane < 7)
                acc = fmaf(h[(size_t)sj * 7 + lane], wj * dd, acc);
        }
    }
    if (lane < 7)
        out[(size_t)d * 7 + lane] = acc;
}

// ---------------------------------------------------------------------------
// launch
// ---------------------------------------------------------------------------
extern "C" void kernel_launch(void* const* d_in, const int* in_sizes, int n_in,
                              void* d_out, int out_size)
{
    const float* x  = (const float*)d_in[0];
    const int*   ei = (const int*)d_in[1];
    const float* W1 = (const float*)d_in[2];
    const float* b1 = (const float*)d_in[3];
    const float* W2 = (const float*)d_in[4];
    const float* b2 = (const float*)d_in[5];
    const float* W3 = (const float*)d_in[6];
    const float* b3 = (const float*)d_in[7];

    int n  = in_sizes[0] / 128;
    int nE = in_sizes[1] / 2;
    float* out = (float*)d_out;

    float *bufA, *bufB, *h3;
    int* degp;
    cudaGetSymbolAddress((void**)&bufA, g_bufA);
    cudaGetSymbolAddress((void**)&bufB, g_bufB);
    cudaGetSymbolAddress((void**)&h3,   g_h3);
    cudaGetSymbolAddress((void**)&degp, g_deg);

    int nb_n = (n + 255) / 256;
    int nb_e = (nE + 255) / 256;
    int nb_g = (n + 63) / 64;
    int nb_w = (int)(((long long)n * 32 + 255) / 256);

    // degree + CSR + dinv (once, reused by all 3 layers)
    cudaMemsetAsync(degp, 0, (size_t)n * sizeof(int));
    k_count_deg<<<nb_e, 256>>>(ei, nE);
    k_scanA<<<nb_n, 256>>>(n);
    k_scanC<<<nb_n, 256>>>(n);
    k_fill<<<nb_e, 256>>>(ei, nE);

    // layer 1: h1 = x@W1 -> bufA ; bufB = agg(h1) + b1
    k_gemm64<128, false><<<nb_g, 256>>>(x, W1, bufA, n);
    k_agg64_csr<<<nb_w, 256>>>(bufA, b1, bufB, n);

    // layer 2: h2 = relu(bufB)@W2 -> bufA ; bufB = agg(h2) + b2
    k_gemm64<64, true><<<nb_g, 256>>>(bufB, W2, bufA, n);
    k_agg64_csr<<<nb_w, 256>>>(bufA, b2, bufB, n);

    // layer 3: h3 = relu(bufB)@W3 ; d_out = agg(h3) + b3
    k_gemm7<<<nb_n, 256>>>(bufB, W3, h3, n);
    k_agg7_csr<<<nb_w, 256>>>(h3, b3, out, n);
}

// round 14
// speedup vs baseline: 1.2725x; 1.0652x over previous
#include <cuda_runtime.h>
#include <stdint.h>

#define N_MAX 100000
#define E_MAX 800000

// Scratch (device globals; no allocation allowed in kernel_launch)
__device__ float g_bufA[(size_t)N_MAX * 64];
__device__ float g_bufB[(size_t)N_MAX * 64];
__device__ float g_h3[(size_t)N_MAX * 7];
__device__ float g_dinv[N_MAX];
__device__ int   g_deg[N_MAX];
__device__ int   g_ptr[N_MAX];
__device__ int   g_fill[N_MAX];
__device__ int   g_csr[E_MAX];
__device__ int   g_blockSums[512];

// ---------------------------------------------------------------------------
// degree (zeroing done by cudaMemsetAsync in kernel_launch)
// ---------------------------------------------------------------------------
__global__ void k_count_deg(const int* __restrict__ ei, int nE) {
    int e = blockIdx.x * blockDim.x + threadIdx.x;
    if (e < nE) atomicAdd(&g_deg[ei[nE + e]], 1);
}

// ---------------------------------------------------------------------------
// CSR build
// ---------------------------------------------------------------------------
__global__ void k_scanA(int n) {
    __shared__ int sh[256];
    int i = blockIdx.x * 256 + threadIdx.x;
    int t = threadIdx.x;
    sh[t] = (i < n) ? g_deg[i] : 0;
    __syncthreads();
    for (int s = 128; s > 0; s >>= 1) {
        if (t < s) sh[t] += sh[t + s];
        __syncthreads();
    }
    if (t == 0) g_blockSums[blockIdx.x] = sh[0];
}

__global__ void k_scanC(int n) {
    __shared__ int sh[256];
    __shared__ int blockOff;
    int i = blockIdx.x * 256 + threadIdx.x;
    int t = threadIdx.x;

    int partial = 0;
    for (int j = t; j < blockIdx.x; j += 256) partial += g_blockSums[j];
    sh[t] = partial;
    __syncthreads();
    for (int s = 128; s > 0; s >>= 1) {
        if (t < s) sh[t] += sh[t + s];
        __syncthreads();
    }
    if (t == 0) blockOff = sh[0];
    __syncthreads();

    int v = (i < n) ? g_deg[i] : 0;
    sh[t] = v;
    __syncthreads();
    for (int off = 1; off < 256; off <<= 1) {
        int x = (t >= off) ? sh[t - off] : 0;
        __syncthreads();
        sh[t] += x;
        __syncthreads();
    }
    if (i < n) {
        int excl = sh[t] - v + blockOff;
        g_ptr[i]  = excl;
        g_fill[i] = excl;
        g_dinv[i] = rsqrtf((float)v + 1.0f);
    }
}

__global__ void k_fill(const int* __restrict__ ei, int nE) {
    int e = blockIdx.x * blockDim.x + threadIdx.x;
    if (e < nE) {
        int s = ei[e];
        int d = ei[nE + e];
        int pos = atomicAdd(&g_fill[d], 1);
        g_csr[pos] = s;
    }
}

// ---------------------------------------------------------------------------
// f32x2 helpers
// ---------------------------------------------------------------------------
__device__ __forceinline__ unsigned long long pack_dup(float v) {
    unsigned long long r;
    asm("mov.b64 %0, {%1, %1};" : "=l"(r) : "f"(v));
    return r;
}
__device__ __forceinline__ void ffma2(unsigned long long& acc,
                                      unsigned long long a,
                                      unsigned long long b) {
    asm("fma.rn.f32x2 %0, %1, %2, %0;" : "+l"(acc) : "l"(a), "l"(b));
}

// ---------------------------------------------------------------------------
// GEMM (R8 shape + xs XOR swizzle): [n x K] @ [K x 64] -> h_out
// ---------------------------------------------------------------------------
template <int K, bool RELU>
__global__ void __launch_bounds__(256) k_gemm64(
    const float* __restrict__ in, const float* __restrict__ W,
    float* __restrict__ h_out, int n)
{
    constexpr int KC = 32;
    __shared__ float xs[KC][72];
    __shared__ float ws[KC][64];

    int tid = threadIdx.x;
    int tx = tid & 15, ty = tid >> 4;
    int rowBase = blockIdx.x * 64;
    int r0 = ty * 4, c0 = tx * 4;

    unsigned long long acc2[4][2];
#pragma unroll
    for (int i = 0; i < 4; i++) { acc2[i][0] = 0ull; acc2[i][1] = 0ull; }

    int lr = tid >> 2;
    int lk = (tid & 3) * 8;

    for (int k0 = 0; k0 < K; k0 += KC) {
        {
            int grow = rowBase + lr;
            float4 v0, v1;
            if (grow < n) {
                const float* p = in + (size_t)grow * K + k0 + lk;
                v0 = *(const float4*)p;
                v1 = *(const float4*)(p + 4);
            } else {
                v0 = make_float4(0.f, 0.f, 0.f, 0.f);
                v1 = v0;
            }
            if (RELU) {
                v0.x = fmaxf(v0.x, 0.f); v0.y = fmaxf(v0.y, 0.f);
                v0.z = fmaxf(v0.z, 0.f); v0.w = fmaxf(v0.w, 0.f);
                v1.x = fmaxf(v1.x, 0.f); v1.y = fmaxf(v1.y, 0.f);
                v1.z = fmaxf(v1.z, 0.f); v1.w = fmaxf(v1.w, 0.f);
            }
            xs[lk + 0][lr ^ ((lk + 0) & 24)] = v0.x;
            xs[lk + 1][lr ^ ((lk + 1) & 24)] = v0.y;
            xs[lk + 2][lr ^ ((lk + 2) & 24)] = v0.z;
            xs[lk + 3][lr ^ ((lk + 3) & 24)] = v0.w;
            xs[lk + 4][lr ^ ((lk + 4) & 24)] = v1.x;
            xs[lk + 5][lr ^ ((lk + 5) & 24)] = v1.y;
            xs[lk + 6][lr ^ ((lk + 6) & 24)] = v1.z;
            xs[lk + 7][lr ^ ((lk + 7) & 24)] = v1.w;
        }
        {
            int lkk = tid >> 3;
            int lc  = (tid & 7) * 8;
            const float* p = W + (size_t)(k0 + lkk) * 64 + lc;
            float4 w0 = *(const float4*)p;
            float4 w1 = *(const float4*)(p + 4);
            *(float4*)&ws[lkk][lc]     = w0;
            *(float4*)&ws[lkk][lc + 4] = w1;
        }
        __syncthreads();
#pragma unroll
        for (int kk = 0; kk < KC; kk++) {
            float4 xv = *(const float4*)&xs[kk][r0 ^ (kk & 24)];
            const unsigned long long* wp =
                (const unsigned long long*)&ws[kk][c0];
            unsigned long long w0 = wp[0], w1 = wp[1];
            unsigned long long x0 = pack_dup(xv.x);
            unsigned long long x1 = pack_dup(xv.y);
            unsigned long long x2 = pack_dup(xv.z);
            unsigned long long x3 = pack_dup(xv.w);
            ffma2(acc2[0][0], x0, w0); ffma2(acc2[0][1], x0, w1);
            ffma2(acc2[1][0], x1, w0); ffma2(acc2[1][1], x1, w1);
            ffma2(acc2[2][0], x2, w0); ffma2(acc2[2][1], x2, w1);
            ffma2(acc2[3][0], x3, w0); ffma2(acc2[3][1], x3, w1);
        }
        __syncthreads();
    }

#pragma unroll
    for (int i = 0; i < 4; i++) {
        int grow = rowBase + r0 + i;
        if (grow < n) {
            float4 hv;
            hv.x = __uint_as_float((unsigned)(acc2[i][0] & 0xffffffffull));
            hv.y = __uint_as_float((unsigned)(acc2[i][0] >> 32));
            hv.z = __uint_as_float((unsigned)(acc2[i][1] & 0xffffffffull));
            hv.w = __uint_as_float((unsigned)(acc2[i][1] >> 32));
            *(float4*)&h_out[(size_t)grow * 64 + c0] = hv;
        }
    }
}

// ---------------------------------------------------------------------------
// CSR pull aggregation (64-wide): one warp per dst node.
// ---------------------------------------------------------------------------
__global__ void __launch_bounds__(256) k_agg64_csr(
    const float* __restrict__ h, const float* __restrict__ b,
    float* __restrict__ out, int n)
{
    int warp = (blockIdx.x * 256 + threadIdx.x) >> 5;
    int lane = threadIdx.x & 31;
    if (warp >= n) return;
    int d = warp;

    float dd = g_dinv[d];
    int start = g_ptr[d];
    int deg   = g_deg[d];

    float2 hv = *(const float2*)(h + (size_t)d * 64 + lane * 2);
    float d2 = dd * dd;
    float2 acc;
    acc.x = fmaf(hv.x, d2, b[lane * 2]);
    acc.y = fmaf(hv.y, d2, b[lane * 2 + 1]);

    for (int base = 0; base < deg; base += 32) {
        int cnt = min(32, deg - base);
        int s = 0; float w = 0.f;
        if (lane < cnt) {
            s = g_csr[start + base + lane];
            w = g_dinv[s];
        }
#pragma unroll 4
        for (int j = 0; j < cnt; j++) {
            int   sj = __shfl_sync(0xffffffffu, s, j);
            float wj = __shfl_sync(0xffffffffu, w, j);
            float coef = wj * dd;
            float2 hs = *(const float2*)(h + (size_t)sj * 64 + lane * 2);
            acc.x = fmaf(hs.x, coef, acc.x);
            acc.y = fmaf(hs.y, coef, acc.y);
        }
    }
    *(float2*)(out + (size_t)d * 64 + lane * 2) = acc;
}

// ---------------------------------------------------------------------------
// Layer 3 GEMM: relu(in[n x 64]) @ W3[64 x 7] -> h3 only
// ---------------------------------------------------------------------------
__global__ void __launch_bounds__(256) k_gemm7(
    const float* __restrict__ in, const float* __restrict__ W,
    float* __restrict__ h_out, int n)
{
    __shared__ float wsh[64 * 7];
    int tid = threadIdx.x;
    for (int i = tid; i < 448; i += 256) wsh[i] = W[i];
    __syncthreads();

    int row = blockIdx.x * blockDim.x + tid;
    if (row >= n) return;

    float acc[7];
#pragma unroll
    for (int c = 0; c < 7; c++) acc[c] = 0.f;

    const float* p = in + (size_t)row * 64;
#pragma unroll
    for (int k = 0; k < 64; k += 4) {
        float4 v = *(const float4*)(p + k);
        v.x = fmaxf(v.x, 0.f); v.y = fmaxf(v.y, 0.f);
        v.z = fmaxf(v.z, 0.f); v.w = fmaxf(v.w, 0.f);
#pragma unroll
        for (int c = 0; c < 7; c++) {
            acc[c] = fmaf(v.x, wsh[(k + 0) * 7 + c], acc[c]);
            acc[c] = fmaf(v.y, wsh[(k + 1) * 7 + c], acc[c]);
            acc[c] = fmaf(v.z, wsh[(k + 2) * 7 + c], acc[c]);
            acc[c] = fmaf(v.w, wsh[(k + 3) * 7 + c], acc[c]);
        }
    }
#pragma unroll
    for (int c = 0; c < 7; c++)
        h_out[(size_t)row * 7 + c] = acc[c];
}

// ---------------------------------------------------------------------------
// CSR pull aggregation (7-wide)
// ---------------------------------------------------------------------------
__global__ void __launch_bounds__(256) k_agg7_csr(
    const float* __restrict__ h, const float* __restrict__ b,
    float* __restrict__ out, int n)
{
    int warp = (blockIdx.x * 256 + threadIdx.x) >> 5;
    int lane = threadIdx.x & 31;
    if (warp >= n) return;
    int d = warp;

    float dd = g_dinv[d];
    int start = g_ptr[d];
    int deg   = g_deg[d];

    float acc = 0.f;
    if (lane < 7)
        acc = fmaf(h[(size_t)d * 7 + lane], dd * dd, b[lane]);

    for (int base = 0; base < deg; base += 32) {
        int cnt = min(32, deg - base);
        int s = 0; float w = 0.f;
        if (lane < cnt) {
            s = g_csr[start + base + lane];
            w = g_dinv[s];
        }
        for (int j = 0; j < cnt; j++) {
            int   sj = __shfl_sync(0xffffffffu, s, j);
            float wj = __shfl_sync(0xffffffffu, w, j);
            if (lane < 7)
                acc = fmaf(h[(size_t)sj * 7 + lane], wj * dd, acc);
        }
    }
    if (lane < 7)
        out[(size_t)d * 7 + lane] = acc;
}

// ---------------------------------------------------------------------------
// launch — CSR build (default stream) overlapped with gemm1 (side stream)
// ---------------------------------------------------------------------------
extern "C" void kernel_launch(void* const* d_in, const int* in_sizes, int n_in,
                              void* d_out, int out_size)
{
    const float* x  = (const float*)d_in[0];
    const int*   ei = (const int*)d_in[1];
    const float* W1 = (const float*)d_in[2];
    const float* b1 = (const float*)d_in[3];
    const float* W2 = (const float*)d_in[4];
    const float* b2 = (const float*)d_in[5];
    const float* W3 = (const float*)d_in[6];
    const float* b3 = (const float*)d_in[7];

    int n  = in_sizes[0] / 128;
    int nE = in_sizes[1] / 2;
    float* out = (float*)d_out;

    float *bufA, *bufB, *h3;
    int* degp;
    cudaGetSymbolAddress((void**)&bufA, g_bufA);
    cudaGetSymbolAddress((void**)&bufB, g_bufB);
    cudaGetSymbolAddress((void**)&h3,   g_h3);
    cudaGetSymbolAddress((void**)&degp, g_deg);

    // one-time host-side objects (no device memory involved)
    static cudaStream_t s2 = nullptr;
    static cudaEvent_t evFork = nullptr, evJoin = nullptr;
    if (!s2) {
        cudaStreamCreateWithFlags(&s2, cudaStreamNonBlocking);
        cudaEventCreateWithFlags(&evFork, cudaEventDisableTiming);
        cudaEventCreateWithFlags(&evJoin, cudaEventDisableTiming);
    }

    int nb_n = (n + 255) / 256;
    int nb_e = (nE + 255) / 256;
    int nb_g = (n + 63) / 64;
    int nb_w = (int)(((long long)n * 32 + 255) / 256);

    // fork: gemm1 on side stream (depends only on x, W1)
    cudaEventRecord(evFork, 0);
    cudaStreamWaitEvent(s2, evFork, 0);
    k_gemm64<128, false><<<nb_g, 256, 0, s2>>>(x, W1, bufA, n);
    cudaEventRecord(evJoin, s2);

    // CSR build on default stream (runs concurrently with gemm1)
    cudaMemsetAsync(degp, 0, (size_t)n * sizeof(int));
    k_count_deg<<<nb_e, 256>>>(ei, nE);
    k_scanA<<<nb_n, 256>>>(n);
    k_scanC<<<nb_n, 256>>>(n);
    k_fill<<<nb_e, 256>>>(ei, nE);

    // join: agg1 needs CSR (stream order) + gemm1 (event)
    cudaStreamWaitEvent(0, evJoin, 0);
    k_agg64_csr<<<nb_w, 256>>>(bufA, b1, bufB, n);

    // layer 2
    k_gemm64<64, true><<<nb_g, 256>>>(bufB, W2, bufA, n);
    k_agg64_csr<<<nb_w, 256>>>(bufA, b2, bufB, n);

    // layer 3
    k_gemm7<<<nb_n, 256>>>(bufB, W3, h3, n);
    k_agg7_csr<<<nb_w, 256>>>(h3, b3, out, n);
}